// round 12
// baseline (speedup 1.0000x reference)
#include <cuda_runtime.h>
#include <cuda_fp16.h>
#include <cstdint>

#define N_ROWS 32768
#define DIM    256
#define NE     8192
#define TM     64
#define TN     64
#define NHALF  (NE / 2)        // 4096 codes per job
#define CH     (NHALF / TN)    // 64 chunks per job

#define NCAND  64              // 32 per codebook half
#define MARGIN 2.5f

#define INDOFF  (N_ROWS * DIM)         // 2097152
#define LOSSOFF (INDOFF + N_ROWS)      // 2129920

// smem layout (bytes)
#define OFF_A    0                      // As2[k][row] dup half2: 256*256 = 65536
#define OFF_B0   65536                  // Bs[k][64 cols] fp16: 256*128 = 32768
#define OFF_B1   98304                  // 32768
#define SMEM_BYTES 131072

// Scratch (device globals: allocation-free per harness rules)
__device__ float  g_embedT[(size_t)NE * DIM];  // [8192][256] fp32 rows
__device__ float  g_norms[NE];                 // ||e_j||^2 exact fp32
__device__ __half g_e16k[(size_t)DIM * NE];    // fp16 codebook k-major [256][8192]
__device__ int    g_cand[(size_t)N_ROWS * NCAND];
__device__ int    g_flag[N_ROWS];
__device__ int    g_idx[N_ROWS];
__device__ float  g_partial[N_ROWS / 64];      // 512 loss partials

// ---------------------------------------------------------------------------
// helpers (base-target PTX only)
// ---------------------------------------------------------------------------
__device__ __forceinline__ uint32_t smem_u32(const void* p) {
    uint32_t a;
    asm("{ .reg .u64 t; cvta.to.shared.u64 t, %1; cvt.u32.u64 %0, t; }"
        : "=r"(a) : "l"(p));
    return a;
}
__device__ __forceinline__ void cpasync16(uint32_t dst, const void* src) {
    asm volatile("cp.async.cg.shared.global [%0], [%1], 16;"
                 :: "r"(dst), "l"(src) : "memory");
}
#define CP_COMMIT() asm volatile("cp.async.commit_group;" ::: "memory")
#define CP_WAIT1()  asm volatile("cp.async.wait_group 1;" ::: "memory")
#define CP_WAIT0()  asm volatile("cp.async.wait_group 0;" ::: "memory")

__device__ __forceinline__ __half2 as_h2(unsigned u) {
    return *reinterpret_cast<const __half2*>(&u);
}

// ---------------------------------------------------------------------------
// Prep: transpose embed [256][8192] -> embedT [8192][256]
// ---------------------------------------------------------------------------
__global__ void vq_transpose(const float* __restrict__ embed) {
    __shared__ float tile[32][33];
    int jB = blockIdx.x * 32, dB = blockIdx.y * 32;
    int tx = threadIdx.x, ty = threadIdx.y;
    #pragma unroll
    for (int r = ty; r < 32; r += 8)
        tile[r][tx] = embed[(size_t)(dB + r) * NE + jB + tx];
    __syncthreads();
    #pragma unroll
    for (int r = ty; r < 32; r += 8)
        g_embedT[(size_t)(jB + r) * DIM + dB + tx] = tile[tx][r];
}

// Prep: norms (identical op order to the rel_err-0.0 R1 kernel)
__global__ void vq_norms() {
    int warp = threadIdx.x >> 5, lane = threadIdx.x & 31;
    int j = blockIdx.x * 8 + warp;
    const float4* row = (const float4*)(g_embedT + (size_t)j * DIM);
    float s = 0.f;
    #pragma unroll
    for (int i = lane; i < DIM / 4; i += 32) {
        float4 v = row[i];
        s += v.x * v.x + v.y * v.y + v.z * v.z + v.w * v.w;
    }
    #pragma unroll
    for (int o = 16; o; o >>= 1) s += __shfl_xor_sync(0xFFFFFFFFu, s, o);
    if (lane == 0) g_norms[j] = s;
}

// Prep: fp32 embed [256][8192] -> fp16 same layout (k-major)
__global__ void vq_convert_e16(const float* __restrict__ embed) {
    int i = blockIdx.x * 256 + threadIdx.x;   // float4 index over 2M floats
    float4 v = ((const float4*)embed)[i];
    __half2* dst = (__half2*)g_e16k;
    dst[i * 2]     = __floats2half2_rn(v.x, v.y);
    dst[i * 2 + 1] = __floats2half2_rn(v.z, v.w);
}

// Prep: reset flags every launch (graph replays!)
__global__ void vq_init() { g_flag[blockIdx.x * 256 + threadIdx.x] = 0; }

// ---------------------------------------------------------------------------
// Main: HFMA2 GEMM screen (2 fp16 MACs/instr) + per-row/lane top-2 + flag.
// grid (512, 2): x = 64-row tile, y = codebook half. 256 threads.
// tx = tid&15 -> 4 cols, ty = tid>>4 -> 4 rows. 8 HFMA2 / k / thread.
// ---------------------------------------------------------------------------
__global__ void __launch_bounds__(256, 1)
vq_main(const float* __restrict__ input) {
    extern __shared__ char smem[];
    const uint32_t sb = smem_u32(smem);

    const int tid = threadIdx.x;
    const int tx = tid & 15, ty = tid >> 4;
    const int lane = tid & 31;
    const int rowBase = blockIdx.x * TM;
    const int colBase = blockIdx.y * NHALF;

    // ---- stage A: fp32 rows -> As2[k][row] duplicated half2 (a,a) ----
    {
        const float4* Ain = (const float4*)(input + (size_t)rowBase * DIM);
        #pragma unroll
        for (int p = 0; p < 16; p++) {
            int v = p * 256 + tid;            // 4096 float4s (64 rows x 64 f4)
            int r  = v >> 6;
            int kb = (v & 63) << 2;
            float4 f = Ain[v];
            *(__half2*)(smem + OFF_A + (kb + 0) * 256 + r * 4) = __float2half2_rn(f.x);
            *(__half2*)(smem + OFF_A + (kb + 1) * 256 + r * 4) = __float2half2_rn(f.y);
            *(__half2*)(smem + OFF_A + (kb + 2) * 256 + r * 4) = __float2half2_rn(f.z);
            *(__half2*)(smem + OFF_A + (kb + 3) * 256 + r * 4) = __float2half2_rn(f.w);
        }
    }

    // ---- B producer: chunk c -> buffer (c&1). 2048 x 16B granules ----
    auto stageB = [&](uint32_t off, int c) {
        const char* base = (const char*)g_e16k + (size_t)(colBase + c * TN) * 2;
        for (int v = tid; v < 2048; v += 256) {
            int k = v >> 3, g = v & 7;        // 256 k-rows x 8 granules (128B)
            cpasync16(sb + off + (uint32_t)k * 128 + g * 16,
                      base + (size_t)k * (NE * 2) + g * 16);
        }
    };
    stageB(OFF_B0, 0);
    CP_COMMIT();

    // per-row top-2 (4 rows/thread) over this lane's 4 cols x 64 chunks
    float cs0[4], cs1[4];
    int   ci0[4], ci1[4];
    #pragma unroll
    for (int r = 0; r < 4; r++) {
        cs0[r] = __int_as_float(0x7F800000);
        cs1[r] = __int_as_float(0x7F800000);
        ci0[r] = 0; ci1[r] = 0;
    }
#define INS(r, sc, jj) do {                                                    \
    float _s = (sc); int _j = (jj);                                            \
    if (_s < cs0[r]) { cs1[r] = cs0[r]; ci1[r] = ci0[r];                       \
                       cs0[r] = _s;     ci0[r] = _j; }                         \
    else if (_s < cs1[r]) { cs1[r] = _s; ci1[r] = _j; }                        \
} while (0)

    for (int c = 0; c < CH; c++) {
        __syncthreads();                      // prior compute on other buf done
        if (c + 1 < CH) {
            stageB((c + 1) & 1 ? OFF_B1 : OFF_B0, c + 1);
            CP_COMMIT();
            CP_WAIT1();                       // chunk c's fill complete
        } else {
            CP_WAIT0();
        }
        __syncthreads();

        const char* Ab = smem + OFF_A;
        const char* Bb = smem + ((c & 1) ? OFF_B1 : OFF_B0);

        // fp32 accumulators per (row, col)
        float accf[4][4];
        #pragma unroll
        for (int r = 0; r < 4; r++)
            #pragma unroll
            for (int j = 0; j < 4; j++) accf[r][j] = 0.f;

        #pragma unroll
        for (int seg = 0; seg < 8; seg++) {   // 8 segs x 32 k, fp16 accum/seg
            __half2 acc[4][2];
            #pragma unroll
            for (int r = 0; r < 4; r++) {
                acc[r][0] = __float2half2_rn(0.f);
                acc[r][1] = __float2half2_rn(0.f);
            }
            #pragma unroll 8
            for (int kk = 0; kk < 32; kk++) {
                const int k = seg * 32 + kk;
                uint4 au = *(const uint4*)(Ab + k * 256 + ty * 16);
                uint2 bu = *(const uint2*)(Bb + k * 128 + tx * 8);
                __half2 b0 = as_h2(bu.x), b1 = as_h2(bu.y);
                __half2 a0 = as_h2(au.x), a1 = as_h2(au.y);
                __half2 a2 = as_h2(au.z), a3 = as_h2(au.w);
                acc[0][0] = __hfma2(a0, b0, acc[0][0]);
                acc[0][1] = __hfma2(a0, b1, acc[0][1]);
                acc[1][0] = __hfma2(a1, b0, acc[1][0]);
                acc[1][1] = __hfma2(a1, b1, acc[1][1]);
                acc[2][0] = __hfma2(a2, b0, acc[2][0]);
                acc[2][1] = __hfma2(a2, b1, acc[2][1]);
                acc[3][0] = __hfma2(a3, b0, acc[3][0]);
                acc[3][1] = __hfma2(a3, b1, acc[3][1]);
            }
            #pragma unroll
            for (int r = 0; r < 4; r++) {
                float2 f0 = __half22float2(acc[r][0]);
                float2 f1 = __half22float2(acc[r][1]);
                accf[r][0] += f0.x; accf[r][1] += f0.y;
                accf[r][2] += f1.x; accf[r][3] += f1.y;
            }
        }

        // epilogue: s = ||e||^2 - 2*dot ; per-row top-2 (ascending j)
        const int jb = colBase + c * TN + tx * 4;
        float4 n4 = *(const float4*)(g_norms + jb);
        float nr[4] = {n4.x, n4.y, n4.z, n4.w};
        #pragma unroll
        for (int j = 0; j < 4; j++) {
            #pragma unroll
            for (int r = 0; r < 4; r++) {
                float s = fmaf(-2.f, accf[r][j], nr[j]);
                INS(r, s, jb + j);
            }
        }
    }
#undef INS

    // ---- per-row flag + candidate write (16 tx lanes per row group) ----
    #pragma unroll
    for (int r = 0; r < 4; r++) {
        float b = cs0[r];
        #pragma unroll
        for (int o = 1; o < 16; o <<= 1)
            b = fminf(b, __shfl_xor_sync(0xFFFFFFFFu, b, o));
        bool f = (cs1[r] <= b + MARGIN);
        unsigned bal = __ballot_sync(0xFFFFFFFFu, f);
        unsigned bits = (bal >> (lane & 16)) & 0xFFFFu;
        const int row = rowBase + ty * 4 + r;
        if (bits && tx == 0) g_flag[row] = 1;   // benign race: both halves write 1
        size_t base = (size_t)row * NCAND + (size_t)blockIdx.y * 32;
        g_cand[base + tx * 2 + 0] = ci0[r];
        g_cand[base + tx * 2 + 1] = ci1[r];
    }
}

// ---------------------------------------------------------------------------
// Refine: exact fp32 scores for 64 candidates (2/lane); flagged rows: full
// vectorized exact scan. One warp per row; first-index tie-break.
// ---------------------------------------------------------------------------
__global__ void __launch_bounds__(256) vq_refine(const float* __restrict__ input,
                                                 float* __restrict__ out) {
    const int wid = threadIdx.x >> 5, lane = threadIdx.x & 31;
    const int row = blockIdx.x * 8 + wid;
    const float4* xp = (const float4*)(input + (size_t)row * DIM);

    float bs = __int_as_float(0x7F800000);
    int   bj = 0x7FFFFFFF;

    if (!g_flag[row]) {
        #pragma unroll
        for (int t = 0; t < 2; t++) {
            const int j = g_cand[(size_t)row * NCAND + t * 32 + lane];
            const float4* ep = (const float4*)(g_embedT + (size_t)j * DIM);
            float p0 = 0.f, p1 = 0.f, p2 = 0.f, p3 = 0.f;
            #pragma unroll 4
            for (int i = 0; i < 64; i += 4) {
                float4 x0 = xp[i],     e0 = ep[i];
                float4 x1 = xp[i + 1], e1 = ep[i + 1];
                float4 x2 = xp[i + 2], e2 = ep[i + 2];
                float4 x3 = xp[i + 3], e3 = ep[i + 3];
                p0 = fmaf(x0.x, e0.x, p0); p0 = fmaf(x0.y, e0.y, p0);
                p0 = fmaf(x0.z, e0.z, p0); p0 = fmaf(x0.w, e0.w, p0);
                p1 = fmaf(x1.x, e1.x, p1); p1 = fmaf(x1.y, e1.y, p1);
                p1 = fmaf(x1.z, e1.z, p1); p1 = fmaf(x1.w, e1.w, p1);
                p2 = fmaf(x2.x, e2.x, p2); p2 = fmaf(x2.y, e2.y, p2);
                p2 = fmaf(x2.z, e2.z, p2); p2 = fmaf(x2.w, e2.w, p2);
                p3 = fmaf(x3.x, e3.x, p3); p3 = fmaf(x3.y, e3.y, p3);
                p3 = fmaf(x3.z, e3.z, p3); p3 = fmaf(x3.w, e3.w, p3);
            }
            float p = (p0 + p1) + (p2 + p3);
            float s = fmaf(-2.f, p, g_norms[j]);
            if (s < bs || (s == bs && j < bj)) { bs = s; bj = j; }
        }
    } else {
        for (int j = lane; j < NE; j += 32) {
            const float4* ep = (const float4*)(g_embedT + (size_t)j * DIM);
            float p0 = 0.f, p1 = 0.f, p2 = 0.f, p3 = 0.f;
            #pragma unroll 4
            for (int i = 0; i < 64; i += 4) {
                float4 x0 = xp[i],     e0 = ep[i];
                float4 x1 = xp[i + 1], e1 = ep[i + 1];
                float4 x2 = xp[i + 2], e2 = ep[i + 2];
                float4 x3 = xp[i + 3], e3 = ep[i + 3];
                p0 = fmaf(x0.x, e0.x, p0); p0 = fmaf(x0.y, e0.y, p0);
                p0 = fmaf(x0.z, e0.z, p0); p0 = fmaf(x0.w, e0.w, p0);
                p1 = fmaf(x1.x, e1.x, p1); p1 = fmaf(x1.y, e1.y, p1);
                p1 = fmaf(x1.z, e1.z, p1); p1 = fmaf(x1.w, e1.w, p1);
                p2 = fmaf(x2.x, e2.x, p2); p2 = fmaf(x2.y, e2.y, p2);
                p2 = fmaf(x2.z, e2.z, p2); p2 = fmaf(x2.w, e2.w, p2);
                p3 = fmaf(x3.x, e3.x, p3); p3 = fmaf(x3.y, e3.y, p3);
                p3 = fmaf(x3.z, e3.z, p3); p3 = fmaf(x3.w, e3.w, p3);
            }
            float p = (p0 + p1) + (p2 + p3);
            float s = fmaf(-2.f, p, g_norms[j]);
            if (s < bs || (s == bs && j < bj)) { bs = s; bj = j; }
        }
    }
    // warp argmin, first-index tie-break (dedups repeated candidates too)
    #pragma unroll
    for (int o = 16; o; o >>= 1) {
        float os = __shfl_xor_sync(0xFFFFFFFFu, bs, o);
        int   oj = __shfl_xor_sync(0xFFFFFFFFu, bj, o);
        if (os < bs || (os == bs && oj < bj)) { bs = os; bj = oj; }
    }
    if (lane == 0) {
        g_idx[row] = bj;
        out[INDOFF + row] = (float)bj;
    }
}

// ---------------------------------------------------------------------------
// Output: gather + straight-through + per-block loss partial
// ---------------------------------------------------------------------------
__global__ void __launch_bounds__(256) vq_output(const float* __restrict__ input,
                                                 float* __restrict__ out) {
    __shared__ int sIdx[64];
    __shared__ float red[256];
    const int tid = threadIdx.x;
    const int rowBase = blockIdx.x * 64;
    if (tid < 64) sIdx[tid] = g_idx[rowBase + tid];
    __syncthreads();
    float lsum = 0.f;
    for (int r = 0; r < 64; r++) {
        int j = sIdx[r];
        float q = g_embedT[(size_t)j * DIM + tid];
        float x = input[(size_t)(rowBase + r) * DIM + tid];
        float d = q - x;
        out[(size_t)(rowBase + r) * DIM + tid] = x + d;   // straight-through
        lsum += d * d;
    }
    red[tid] = lsum;
    __syncthreads();
    #pragma unroll
    for (int s = 128; s; s >>= 1) {
        if (tid < s) red[tid] += red[tid + s];
        __syncthreads();
    }
    if (tid == 0) g_partial[blockIdx.x] = red[0];
}

__global__ void vq_loss_final(float* __restrict__ out) {
    __shared__ float red[512];
    red[threadIdx.x] = g_partial[threadIdx.x];
    __syncthreads();
    #pragma unroll
    for (int s = 256; s; s >>= 1) {
        if (threadIdx.x < s) red[threadIdx.x] += red[threadIdx.x + s];
        __syncthreads();
    }
    if (threadIdx.x == 0)
        out[LOSSOFF] = red[0] * (1.0f / (float)(N_ROWS * DIM));
}

// ---------------------------------------------------------------------------
extern "C" void kernel_launch(void* const* d_in, const int* in_sizes, int n_in,
                              void* d_out, int out_size) {
    const float* input = (const float*)d_in[0];   // [8,64,64,256]
    const float* embed = (const float*)d_in[1];   // [256,8192]
    float* out = (float*)d_out;

    cudaFuncSetAttribute(vq_main, cudaFuncAttributeMaxDynamicSharedMemorySize,
                         SMEM_BYTES);

    vq_transpose<<<dim3(NE / 32, DIM / 32), dim3(32, 8)>>>(embed);
    vq_norms<<<NE / 8, 256>>>();
    vq_convert_e16<<<(NE * DIM / 4) / 256, 256>>>(embed);
    vq_init<<<N_ROWS / 256, 256>>>();
    vq_main<<<dim3(N_ROWS / TM, 2), 256, SMEM_BYTES>>>(input);
    vq_refine<<<N_ROWS / 8, 256>>>(input, out);
    vq_output<<<N_ROWS / 64, 256>>>(input, out);
    vq_loss_final<<<1, 512>>>(out);
}

// round 13
// speedup vs baseline: 2.1305x; 2.1305x over previous
#include <cuda_runtime.h>
#include <cstdint>

#define N_ROWS 32768
#define DIM    256
#define NE     8192
#define TM     64
#define TN     64
#define NHALF  (NE / 2)        // 4096 codes per job
#define CH     (NHALF / TN)    // 64 chunks per job

#define INDOFF  (N_ROWS * DIM)         // 2097152
#define LOSSOFF (INDOFF + N_ROWS)      // 2129920

// Scratch (device globals: allocation-free per harness rules)
__device__ float              g_embedT[(size_t)NE * DIM]; // [8192][256]
__device__ float              g_norms[NE];                // ||e_j||^2
__device__ unsigned long long g_best[N_ROWS];             // packed (key, idx)
__device__ int                g_idx[N_ROWS];
__device__ float              g_partial[N_ROWS / 64];     // 512 loss partials

// ---------------------------------------------------------------------------
// Prep: transpose embed [256][8192] -> embedT [8192][256]
// ---------------------------------------------------------------------------
__global__ void vq_transpose(const float* __restrict__ embed) {
    __shared__ float tile[32][33];
    int jB = blockIdx.x * 32, dB = blockIdx.y * 32;
    int tx = threadIdx.x, ty = threadIdx.y;
    #pragma unroll
    for (int r = ty; r < 32; r += 8)
        tile[r][tx] = embed[(size_t)(dB + r) * NE + jB + tx];
    __syncthreads();
    #pragma unroll
    for (int r = ty; r < 32; r += 8)
        g_embedT[(size_t)(jB + r) * DIM + dB + tx] = tile[tx][r];
}

// Prep: norms (identical op order to the rel_err-0.0 R1 kernel)
__global__ void vq_norms() {
    int warp = threadIdx.x >> 5, lane = threadIdx.x & 31;
    int j = blockIdx.x * 8 + warp;
    const float4* row = (const float4*)(g_embedT + (size_t)j * DIM);
    float s = 0.f;
    #pragma unroll
    for (int i = lane; i < DIM / 4; i += 32) {
        float4 v = row[i];
        s += v.x * v.x + v.y * v.y + v.z * v.z + v.w * v.w;
    }
    #pragma unroll
    for (int o = 16; o; o >>= 1) s += __shfl_xor_sync(0xFFFFFFFFu, s, o);
    if (lane == 0) g_norms[j] = s;
}

// Prep: reset global argmin slots every launch (graph replays!)
__global__ void vq_init() {
    g_best[blockIdx.x * 256 + threadIdx.x] = 0xFFFFFFFFFFFFFFFFull;
}

// ---------------------------------------------------------------------------
// Main: R1's FFMA GEMM + fused argmin, VERBATIM inner loop & staging.
// Only change: each CTA scans HALF the codebook; grid (512, 2);
// halves combined via global packed atomicMin.
// ---------------------------------------------------------------------------
__global__ void __launch_bounds__(256, 1)
vq_main(const float* __restrict__ input, const float* __restrict__ embed,
        float* __restrict__ out) {
    extern __shared__ float smem[];
    float* As = smem;                    // [256][64] : As[k*64 + m]
    float* Bs = smem + 256 * 64;         // [256][64] : Bs[k*64 + j]
    unsigned long long* bestP = (unsigned long long*)(smem + 2 * 256 * 64); // 64

    const int tid = threadIdx.x;
    const int tx  = tid & 15;            // 0..15 -> 4 cols each
    const int ty  = tid >> 4;            // 0..15 -> 4 rows each
    const int rowBase = blockIdx.x * TM;
    const int colBase = blockIdx.y * NHALF;

    if (tid < TM) bestP[tid] = 0xFFFFFFFFFFFFFFFFull;

    // ---- stage A once: input rows rowBase..rowBase+63, stored transposed ----
    {
        const float4* Ain = (const float4*)(input + (size_t)rowBase * DIM);
        #pragma unroll
        for (int p = 0; p < 16; p++) {
            int f4 = p * 256 + tid;        // 0..4095 float4s (64 rows x 64 f4)
            int r  = f4 >> 6;              // row within tile
            int kb = (f4 & 63) << 2;       // k base
            float4 v = Ain[f4];
            As[(kb + 0) * TM + r] = v.x;
            As[(kb + 1) * TM + r] = v.y;
            As[(kb + 2) * TM + r] = v.z;
            As[(kb + 3) * TM + r] = v.w;
        }
    }

    unsigned int bKey[4];
    int bIdx[4];
    #pragma unroll
    for (int i = 0; i < 4; i++) { bKey[i] = 0xFFFFFFFFu; bIdx[i] = 0; }

    for (int c = 0; c < CH; c++) {
        const int cb = colBase + c * TN;
        __syncthreads();   // previous chunk's compute done before Bs overwrite
        {
            const float* Bsrc = embed + cb;   // embed[k][j] row-major stride NE
            #pragma unroll
            for (int p = 0; p < 16; p++) {
                int f4 = p * 256 + tid;       // 4096 float4s (256 k x 16 f4)
                int k  = f4 >> 4;
                int jb = (f4 & 15) << 2;
                *(float4*)(Bs + k * TN + jb) =
                    *(const float4*)(Bsrc + (size_t)k * NE + jb);
            }
        }
        __syncthreads();

        float acc[4][4] = {};
        #pragma unroll 8
        for (int k = 0; k < DIM; k++) {
            float4 av = *(const float4*)(As + k * TM + (ty << 2));
            float4 bv = *(const float4*)(Bs + k * TN + (tx << 2));
            float a_[4] = {av.x, av.y, av.z, av.w};
            float b_[4] = {bv.x, bv.y, bv.z, bv.w};
            #pragma unroll
            for (int i = 0; i < 4; i++)
                #pragma unroll
                for (int jj = 0; jj < 4; jj++)
                    acc[i][jj] = fmaf(a_[i], b_[jj], acc[i][jj]);
        }

        // epilogue: score = ||e||^2 - 2*dot ; argmin with first-index ties
        #pragma unroll
        for (int jj = 0; jj < 4; jj++) {
            int jg = cb + (tx << 2) + jj;
            float nrm = g_norms[jg];
            #pragma unroll
            for (int i = 0; i < 4; i++) {
                float s = fmaf(-2.f, acc[i][jj], nrm);
                unsigned u = __float_as_uint(s);
                unsigned key = (u & 0x80000000u) ? ~u : (u | 0x80000000u);
                if (key < bKey[i]) { bKey[i] = key; bIdx[i] = jg; }
            }
        }
    }

    // ---- combine argmin: smem across threads, then global across halves ----
    #pragma unroll
    for (int i = 0; i < 4; i++) {
        unsigned long long p =
            ((unsigned long long)bKey[i] << 32) | (unsigned)bIdx[i];
        atomicMin(&bestP[(ty << 2) + i], p);
    }
    __syncthreads();

    if (tid < TM)
        atomicMin(&g_best[rowBase + tid], bestP[tid]);
}

// ---------------------------------------------------------------------------
// Finalize indices
// ---------------------------------------------------------------------------
__global__ void vq_fin(float* __restrict__ out) {
    int row = blockIdx.x * 256 + threadIdx.x;
    int j = (int)(g_best[row] & 0xFFFFFFFFull);
    g_idx[row] = j;
    out[INDOFF + row] = (float)j;
}

// ---------------------------------------------------------------------------
// Output: gather + straight-through + per-block loss partial
// ---------------------------------------------------------------------------
__global__ void __launch_bounds__(256) vq_output(const float* __restrict__ input,
                                                 float* __restrict__ out) {
    __shared__ int sIdx[64];
    __shared__ float red[256];
    const int tid = threadIdx.x;
    const int rowBase = blockIdx.x * 64;
    if (tid < 64) sIdx[tid] = g_idx[rowBase + tid];
    __syncthreads();
    float lsum = 0.f;
    for (int r = 0; r < 64; r++) {
        int j = sIdx[r];
        float q = g_embedT[(size_t)j * DIM + tid];
        float x = input[(size_t)(rowBase + r) * DIM + tid];
        float d = q - x;
        out[(size_t)(rowBase + r) * DIM + tid] = x + d;   // straight-through
        lsum += d * d;
    }
    red[tid] = lsum;
    __syncthreads();
    #pragma unroll
    for (int s = 128; s; s >>= 1) {
        if (tid < s) red[tid] += red[tid + s];
        __syncthreads();
    }
    if (tid == 0) g_partial[blockIdx.x] = red[0];
}

__global__ void vq_loss_final(float* __restrict__ out) {
    __shared__ float red[512];
    red[threadIdx.x] = g_partial[threadIdx.x];
    __syncthreads();
    #pragma unroll
    for (int s = 256; s; s >>= 1) {
        if (threadIdx.x < s) red[threadIdx.x] += red[threadIdx.x + s];
        __syncthreads();
    }
    if (threadIdx.x == 0)
        out[LOSSOFF] = red[0] * (1.0f / (float)(N_ROWS * DIM));
}

// ---------------------------------------------------------------------------
extern "C" void kernel_launch(void* const* d_in, const int* in_sizes, int n_in,
                              void* d_out, int out_size) {
    const float* input = (const float*)d_in[0];   // [8,64,64,256]
    const float* embed = (const float*)d_in[1];   // [256,8192]
    float* out = (float*)d_out;

    const int smemBytes = (2 * 256 * 64) * 4 + 64 * 8;   // As + Bs + bestP
    cudaFuncSetAttribute(vq_main, cudaFuncAttributeMaxDynamicSharedMemorySize,
                         smemBytes);

    vq_transpose<<<dim3(NE / 32, DIM / 32), dim3(32, 8)>>>(embed);
    vq_norms<<<NE / 8, 256>>>();
    vq_init<<<N_ROWS / 256, 256>>>();
    vq_main<<<dim3(N_ROWS / TM, 2), 256, smemBytes>>>(input, embed, out);
    vq_fin<<<N_ROWS / 256, 256>>>(out);
    vq_output<<<N_ROWS / 64, 256>>>(input, out);
    vq_loss_final<<<1, 512>>>(out);
}

// round 15
// speedup vs baseline: 2.4951x; 1.1712x over previous
#include <cuda_runtime.h>
#include <cstdint>

#define N_ROWS 32768
#define DIM    256
#define NE     8192
#define TM     128
#define TN     64
#define NSPLIT 4
#define NQ     (NE / NSPLIT)   // 2048 codes per job
#define CH     (NQ / TN)       // 32 chunks per job

#define INDOFF  (N_ROWS * DIM)         // 2097152
#define LOSSOFF (INDOFF + N_ROWS)      // 2129920

// Scratch (device globals: allocation-free per harness rules)
__device__ float              g_embedT[(size_t)NE * DIM]; // [8192][256]
__device__ float              g_norms[NE];                // ||e_j||^2
__device__ unsigned long long g_best[N_ROWS];             // packed (key, idx)
__device__ int                g_idx[N_ROWS];
__device__ float              g_partial[N_ROWS / 64];     // 512 loss partials

// ---------------------------------------------------------------------------
// Prep: transpose embed [256][8192] -> embedT [8192][256]
// ---------------------------------------------------------------------------
__global__ void vq_transpose(const float* __restrict__ embed) {
    __shared__ float tile[32][33];
    int jB = blockIdx.x * 32, dB = blockIdx.y * 32;
    int tx = threadIdx.x, ty = threadIdx.y;
    #pragma unroll
    for (int r = ty; r < 32; r += 8)
        tile[r][tx] = embed[(size_t)(dB + r) * NE + jB + tx];
    __syncthreads();
    #pragma unroll
    for (int r = ty; r < 32; r += 8)
        g_embedT[(size_t)(jB + r) * DIM + dB + tx] = tile[tx][r];
}

// Prep: norms (identical op order to the rel_err-0.0 R1 kernel)
__global__ void vq_norms() {
    int warp = threadIdx.x >> 5, lane = threadIdx.x & 31;
    int j = blockIdx.x * 8 + warp;
    const float4* row = (const float4*)(g_embedT + (size_t)j * DIM);
    float s = 0.f;
    #pragma unroll
    for (int i = lane; i < DIM / 4; i += 32) {
        float4 v = row[i];
        s += v.x * v.x + v.y * v.y + v.z * v.z + v.w * v.w;
    }
    #pragma unroll
    for (int o = 16; o; o >>= 1) s += __shfl_xor_sync(0xFFFFFFFFu, s, o);
    if (lane == 0) g_norms[j] = s;
}

// Prep: reset global argmin slots every launch (graph replays!)
__global__ void vq_init() {
    g_best[blockIdx.x * 256 + threadIdx.x] = 0xFFFFFFFFFFFFFFFFull;
}

// ---------------------------------------------------------------------------
// Main: FFMA GEMM + fused argmin. 8x4 microtile (1.5 B LDS per FMA).
// grid (256, 4): x = 128-row tile, y = codebook quarter. 256 threads.
// tx = tid&15 -> 4 cols, ty = tid>>4 -> 8 rows.
// ---------------------------------------------------------------------------
__global__ void __launch_bounds__(256, 1)
vq_main(const float* __restrict__ input, const float* __restrict__ embed) {
    extern __shared__ float smem[];
    float* As = smem;                    // [256][128] : As[k*128 + m]  (128 KB)
    float* Bs = smem + 256 * 128;        // [256][64]  : Bs[k*64 + j]   (64 KB)
    unsigned long long* bestP =
        (unsigned long long*)(smem + 256 * 128 + 256 * 64);            // 128

    const int tid = threadIdx.x;
    const int tx  = tid & 15;            // 4 cols each
    const int ty  = tid >> 4;            // 8 rows each
    const int rowBase = blockIdx.x * TM;
    const int colBase = blockIdx.y * NQ;

    if (tid < TM) bestP[tid] = 0xFFFFFFFFFFFFFFFFull;

    // ---- stage A once: 128 rows, stored transposed As[k][m] ----
    {
        const float4* Ain = (const float4*)(input + (size_t)rowBase * DIM);
        #pragma unroll
        for (int p = 0; p < 32; p++) {
            int f4 = p * 256 + tid;        // 8192 float4s (128 rows x 64 f4)
            int r  = f4 >> 6;              // row within tile
            int kb = (f4 & 63) << 2;       // k base
            float4 v = Ain[f4];
            As[(kb + 0) * TM + r] = v.x;
            As[(kb + 1) * TM + r] = v.y;
            As[(kb + 2) * TM + r] = v.z;
            As[(kb + 3) * TM + r] = v.w;
        }
    }

    unsigned int bKey[8];
    int bIdx[8];
    #pragma unroll
    for (int i = 0; i < 8; i++) { bKey[i] = 0xFFFFFFFFu; bIdx[i] = 0; }

    for (int c = 0; c < CH; c++) {
        const int cb = colBase + c * TN;
        __syncthreads();   // previous chunk's compute done before Bs overwrite
        {
            const float* Bsrc = embed + cb;   // embed[k][j] row-major stride NE
            #pragma unroll
            for (int p = 0; p < 16; p++) {
                int f4 = p * 256 + tid;       // 4096 float4s (256 k x 16 f4)
                int k  = f4 >> 4;
                int jb = (f4 & 15) << 2;
                *(float4*)(Bs + k * TN + jb) =
                    *(const float4*)(Bsrc + (size_t)k * NE + jb);
            }
        }
        __syncthreads();

        float acc[8][4] = {};
        #pragma unroll 4
        for (int k = 0; k < DIM; k++) {
            float4 a0 = *(const float4*)(As + k * TM + (ty << 3));
            float4 a1 = *(const float4*)(As + k * TM + (ty << 3) + 4);
            float4 bv = *(const float4*)(Bs + k * TN + (tx << 2));
            float a_[8] = {a0.x, a0.y, a0.z, a0.w, a1.x, a1.y, a1.z, a1.w};
            float b_[4] = {bv.x, bv.y, bv.z, bv.w};
            #pragma unroll
            for (int i = 0; i < 8; i++)
                #pragma unroll
                for (int jj = 0; jj < 4; jj++)
                    acc[i][jj] = fmaf(a_[i], b_[jj], acc[i][jj]);
        }

        // epilogue: score = ||e||^2 - 2*dot ; argmin with first-index ties
        #pragma unroll
        for (int jj = 0; jj < 4; jj++) {
            int jg = cb + (tx << 2) + jj;
            float nrm = g_norms[jg];
            #pragma unroll
            for (int i = 0; i < 8; i++) {
                float s = fmaf(-2.f, acc[i][jj], nrm);
                unsigned u = __float_as_uint(s);
                unsigned key = (u & 0x80000000u) ? ~u : (u | 0x80000000u);
                if (key < bKey[i]) { bKey[i] = key; bIdx[i] = jg; }
            }
        }
    }

    // ---- combine argmin: smem across threads, then global across splits ----
    #pragma unroll
    for (int i = 0; i < 8; i++) {
        unsigned long long p =
            ((unsigned long long)bKey[i] << 32) | (unsigned)bIdx[i];
        atomicMin(&bestP[(ty << 3) + i], p);
    }
    __syncthreads();

    if (tid < TM)
        atomicMin(&g_best[rowBase + tid], bestP[tid]);
}

// ---------------------------------------------------------------------------
// Finalize indices
// ---------------------------------------------------------------------------
__global__ void vq_fin(float* __restrict__ out) {
    int row = blockIdx.x * 256 + threadIdx.x;
    int j = (int)(g_best[row] & 0xFFFFFFFFull);
    g_idx[row] = j;
    out[INDOFF + row] = (float)j;
}

// ---------------------------------------------------------------------------
// Output: gather + straight-through + per-block loss partial
// ---------------------------------------------------------------------------
__global__ void __launch_bounds__(256) vq_output(const float* __restrict__ input,
                                                 float* __restrict__ out) {
    __shared__ int sIdx[64];
    __shared__ float red[256];
    const int tid = threadIdx.x;
    const int rowBase = blockIdx.x * 64;
    if (tid < 64) sIdx[tid] = g_idx[rowBase + tid];
    __syncthreads();
    float lsum = 0.f;
    for (int r = 0; r < 64; r++) {
        int j = sIdx[r];
        float q = g_embedT[(size_t)j * DIM + tid];
        float x = input[(size_t)(rowBase + r) * DIM + tid];
        float d = q - x;
        out[(size_t)(rowBase + r) * DIM + tid] = x + d;   // straight-through
        lsum += d * d;
    }
    red[tid] = lsum;
    __syncthreads();
    #pragma unroll
    for (int s = 128; s; s >>= 1) {
        if (tid < s) red[tid] += red[tid + s];
        __syncthreads();
    }
    if (tid == 0) g_partial[blockIdx.x] = red[0];
}

__global__ void vq_loss_final(float* __restrict__ out) {
    __shared__ float red[512];
    red[threadIdx.x] = g_partial[threadIdx.x];
    __syncthreads();
    #pragma unroll
    for (int s = 256; s; s >>= 1) {
        if (threadIdx.x < s) red[threadIdx.x] += red[threadIdx.x + s];
        __syncthreads();
    }
    if (threadIdx.x == 0)
        out[LOSSOFF] = red[0] * (1.0f / (float)(N_ROWS * DIM));
}

// ---------------------------------------------------------------------------
extern "C" void kernel_launch(void* const* d_in, const int* in_sizes, int n_in,
                              void* d_out, int out_size) {
    const float* input = (const float*)d_in[0];   // [8,64,64,256]
    const float* embed = (const float*)d_in[1];   // [256,8192]
    float* out = (float*)d_out;

    const int smemBytes = (256 * 128 + 256 * 64) * 4 + 128 * 8;
    cudaFuncSetAttribute(vq_main, cudaFuncAttributeMaxDynamicSharedMemorySize,
                         smemBytes);

    vq_transpose<<<dim3(NE / 32, DIM / 32), dim3(32, 8)>>>(embed);
    vq_norms<<<NE / 8, 256>>>();
    vq_init<<<N_ROWS / 256, 256>>>();
    vq_main<<<dim3(N_ROWS / TM, NSPLIT), 256, smemBytes>>>(input, embed);
    vq_fin<<<N_ROWS / 256, 256>>>(out);
    vq_output<<<N_ROWS / 64, 256>>>(input, out);
    vq_loss_final<<<1, 512>>>(out);
}

// round 16
// speedup vs baseline: 2.6966x; 1.0807x over previous
#include <cuda_runtime.h>
#include <cstdint>

#define N_ROWS 32768
#define DIM    256
#define NE     8192
#define TM     128
#define TN     128
#define NSPLIT 4
#define NQ     (NE / NSPLIT)   // 2048 codes per job
#define CH     (NQ / TN)       // 16 chunks per job

#define INDOFF  (N_ROWS * DIM)         // 2097152
#define LOSSOFF (INDOFF + N_ROWS)      // 2129920

// Scratch (device globals: allocation-free per harness rules)
__device__ float              g_embedT[(size_t)NE * DIM]; // [8192][256]
__device__ float              g_norms[NE];                // ||e_j||^2
__device__ unsigned long long g_best[N_ROWS];             // packed (key, idx)
__device__ int                g_idx[N_ROWS];
__device__ float              g_partial[N_ROWS / 64];     // 512 loss partials

// ---------------------------------------------------------------------------
// Prep: transpose embed [256][8192] -> embedT [8192][256]
// ---------------------------------------------------------------------------
__global__ void vq_transpose(const float* __restrict__ embed) {
    __shared__ float tile[32][33];
    int jB = blockIdx.x * 32, dB = blockIdx.y * 32;
    int tx = threadIdx.x, ty = threadIdx.y;
    #pragma unroll
    for (int r = ty; r < 32; r += 8)
        tile[r][tx] = embed[(size_t)(dB + r) * NE + jB + tx];
    __syncthreads();
    #pragma unroll
    for (int r = ty; r < 32; r += 8)
        g_embedT[(size_t)(jB + r) * DIM + dB + tx] = tile[tx][r];
}

// Prep: norms (identical op order to the rel_err-0.0 R1 kernel)
__global__ void vq_norms() {
    int warp = threadIdx.x >> 5, lane = threadIdx.x & 31;
    int j = blockIdx.x * 8 + warp;
    const float4* row = (const float4*)(g_embedT + (size_t)j * DIM);
    float s = 0.f;
    #pragma unroll
    for (int i = lane; i < DIM / 4; i += 32) {
        float4 v = row[i];
        s += v.x * v.x + v.y * v.y + v.z * v.z + v.w * v.w;
    }
    #pragma unroll
    for (int o = 16; o; o >>= 1) s += __shfl_xor_sync(0xFFFFFFFFu, s, o);
    if (lane == 0) g_norms[j] = s;
}

// Prep: reset global argmin slots every launch (graph replays!)
__global__ void vq_init() {
    g_best[blockIdx.x * 256 + threadIdx.x] = 0xFFFFFFFFFFFFFFFFull;
}

// ---------------------------------------------------------------------------
// Main: FFMA GEMM + fused argmin. 8x8 microtile (1.0 B LDS per FMA).
// grid (256, 4): x = 128-row tile, y = codebook quarter. 256 threads.
// tx = tid&15 -> 8 cols, ty = tid>>4 -> 8 rows.
// B staged per chunk in TWO k-halves (64 KB buffer); acc persists in regs.
// ---------------------------------------------------------------------------
__global__ void __launch_bounds__(256, 1)
vq_main(const float* __restrict__ input, const float* __restrict__ embed) {
    extern __shared__ float smem[];
    float* As = smem;                    // [256][128] : As[k*128 + m]  (128 KB)
    float* Bs = smem + 256 * 128;        // [128][128] : Bs[kk*128 + j] (64 KB)
    unsigned long long* bestP =
        (unsigned long long*)(smem + 256 * 128 + 128 * 128);           // 128

    const int tid = threadIdx.x;
    const int tx  = tid & 15;            // 8 cols each
    const int ty  = tid >> 4;            // 8 rows each
    const int rowBase = blockIdx.x * TM;
    const int colBase = blockIdx.y * NQ;

    if (tid < TM) bestP[tid] = 0xFFFFFFFFFFFFFFFFull;

    // ---- stage A once: 128 rows, stored transposed As[k][m] ----
    {
        const float4* Ain = (const float4*)(input + (size_t)rowBase * DIM);
        #pragma unroll
        for (int p = 0; p < 32; p++) {
            int f4 = p * 256 + tid;        // 8192 float4s (128 rows x 64 f4)
            int r  = f4 >> 6;              // row within tile
            int kb = (f4 & 63) << 2;       // k base
            float4 v = Ain[f4];
            As[(kb + 0) * TM + r] = v.x;
            As[(kb + 1) * TM + r] = v.y;
            As[(kb + 2) * TM + r] = v.z;
            As[(kb + 3) * TM + r] = v.w;
        }
    }

    unsigned int bKey[8];
    int bIdx[8];
    #pragma unroll
    for (int i = 0; i < 8; i++) { bKey[i] = 0xFFFFFFFFu; bIdx[i] = 0; }

    for (int c = 0; c < CH; c++) {
        const int cb = colBase + c * TN;

        float acc[8][8];
        #pragma unroll
        for (int i = 0; i < 8; i++)
            #pragma unroll
            for (int jj = 0; jj < 8; jj++) acc[i][jj] = 0.f;

        #pragma unroll
        for (int h = 0; h < 2; h++) {
            __syncthreads();   // previous compute done before Bs overwrite
            {
                // stage B k-half: rows h*128..h*128+127, cols cb..cb+127
                const float* Bsrc = embed + (size_t)(h * 128) * NE + cb;
                #pragma unroll
                for (int p = 0; p < 16; p++) {
                    int f4 = p * 256 + tid;   // 4096 float4s (128 k x 32 f4)
                    int k  = f4 >> 5;
                    int jb = (f4 & 31) << 2;
                    *(float4*)(Bs + k * TN + jb) =
                        *(const float4*)(Bsrc + (size_t)k * NE + jb);
                }
            }
            __syncthreads();

            const float* Ah = As + (h * 128) * TM;
            #pragma unroll 4
            for (int kk = 0; kk < 128; kk++) {
                float4 a0 = *(const float4*)(Ah + kk * TM + (ty << 3));
                float4 a1 = *(const float4*)(Ah + kk * TM + (ty << 3) + 4);
                float4 b0 = *(const float4*)(Bs + kk * TN + (tx << 3));
                float4 b1 = *(const float4*)(Bs + kk * TN + (tx << 3) + 4);
                float a_[8] = {a0.x, a0.y, a0.z, a0.w, a1.x, a1.y, a1.z, a1.w};
                float b_[8] = {b0.x, b0.y, b0.z, b0.w, b1.x, b1.y, b1.z, b1.w};
                #pragma unroll
                for (int i = 0; i < 8; i++)
                    #pragma unroll
                    for (int jj = 0; jj < 8; jj++)
                        acc[i][jj] = fmaf(a_[i], b_[jj], acc[i][jj]);
            }
        }

        // epilogue: score = ||e||^2 - 2*dot ; argmin with first-index ties
        #pragma unroll
        for (int jj = 0; jj < 8; jj++) {
            int jg = cb + (tx << 3) + jj;
            float nrm = g_norms[jg];
            #pragma unroll
            for (int i = 0; i < 8; i++) {
                float s = fmaf(-2.f, acc[i][jj], nrm);
                unsigned u = __float_as_uint(s);
                unsigned key = (u & 0x80000000u) ? ~u : (u | 0x80000000u);
                if (key < bKey[i]) { bKey[i] = key; bIdx[i] = jg; }
            }
        }
    }

    // ---- combine argmin: smem across threads, then global across splits ----
    #pragma unroll
    for (int i = 0; i < 8; i++) {
        unsigned long long p =
            ((unsigned long long)bKey[i] << 32) | (unsigned)bIdx[i];
        atomicMin(&bestP[(ty << 3) + i], p);
    }
    __syncthreads();

    if (tid < TM)
        atomicMin(&g_best[rowBase + tid], bestP[tid]);
}

// ---------------------------------------------------------------------------
// Finalize indices
// ---------------------------------------------------------------------------
__global__ void vq_fin(float* __restrict__ out) {
    int row = blockIdx.x * 256 + threadIdx.x;
    int j = (int)(g_best[row] & 0xFFFFFFFFull);
    g_idx[row] = j;
    out[INDOFF + row] = (float)j;
}

// ---------------------------------------------------------------------------
// Output: gather + straight-through + per-block loss partial
// ---------------------------------------------------------------------------
__global__ void __launch_bounds__(256) vq_output(const float* __restrict__ input,
                                                 float* __restrict__ out) {
    __shared__ int sIdx[64];
    __shared__ float red[256];
    const int tid = threadIdx.x;
    const int rowBase = blockIdx.x * 64;
    if (tid < 64) sIdx[tid] = g_idx[rowBase + tid];
    __syncthreads();
    float lsum = 0.f;
    for (int r = 0; r < 64; r++) {
        int j = sIdx[r];
        float q = g_embedT[(size_t)j * DIM + tid];
        float x = input[(size_t)(rowBase + r) * DIM + tid];
        float d = q - x;
        out[(size_t)(rowBase + r) * DIM + tid] = x + d;   // straight-through
        lsum += d * d;
    }
    red[tid] = lsum;
    __syncthreads();
    #pragma unroll
    for (int s = 128; s; s >>= 1) {
        if (tid < s) red[tid] += red[tid + s];
        __syncthreads();
    }
    if (tid == 0) g_partial[blockIdx.x] = red[0];
}

__global__ void vq_loss_final(float* __restrict__ out) {
    __shared__ float red[512];
    red[threadIdx.x] = g_partial[threadIdx.x];
    __syncthreads();
    #pragma unroll
    for (int s = 256; s; s >>= 1) {
        if (threadIdx.x < s) red[threadIdx.x] += red[threadIdx.x + s];
        __syncthreads();
    }
    if (threadIdx.x == 0)
        out[LOSSOFF] = red[0] * (1.0f / (float)(N_ROWS * DIM));
}

// ---------------------------------------------------------------------------
extern "C" void kernel_launch(void* const* d_in, const int* in_sizes, int n_in,
                              void* d_out, int out_size) {
    const float* input = (const float*)d_in[0];   // [8,64,64,256]
    const float* embed = (const float*)d_in[1];   // [256,8192]
    float* out = (float*)d_out;

    const int smemBytes = (256 * 128 + 128 * 128) * 4 + 128 * 8;
    cudaFuncSetAttribute(vq_main, cudaFuncAttributeMaxDynamicSharedMemorySize,
                         smemBytes);

    vq_transpose<<<dim3(NE / 32, DIM / 32), dim3(32, 8)>>>(embed);
    vq_norms<<<NE / 8, 256>>>();
    vq_init<<<N_ROWS / 256, 256>>>();
    vq_main<<<dim3(N_ROWS / TM, NSPLIT), 256, smemBytes>>>(input, embed);
    vq_fin<<<N_ROWS / 256, 256>>>(out);
    vq_output<<<N_ROWS / 64, 256>>>(input, out);
    vq_loss_final<<<1, 512>>>(out);
}

// round 17
// speedup vs baseline: 2.7415x; 1.0167x over previous
#include <cuda_runtime.h>
#include <cstdint>

#define N_ROWS 32768
#define DIM    256
#define NE     8192
#define TM     128
#define TN     128
#define NSPLIT 4
#define NQ     (NE / NSPLIT)   // 2048 codes per job
#define CH     (NQ / TN)       // 16 chunks per job

#define INDOFF  (N_ROWS * DIM)         // 2097152
#define LOSSOFF (INDOFF + N_ROWS)      // 2129920

// Scratch (device globals: allocation-free per harness rules)
__device__ float              g_embedT[(size_t)NE * DIM]; // [8192][256]
__device__ float              g_norms[NE];                // ||e_j||^2
__device__ unsigned long long g_best[N_ROWS];             // packed (key, idx)
__device__ int                g_idx[N_ROWS];
__device__ float              g_partial[N_ROWS / 64];     // 512 loss partials

// ---------------------------------------------------------------------------
// helpers (base-target PTX only)
// ---------------------------------------------------------------------------
__device__ __forceinline__ uint32_t smem_u32(const void* p) {
    uint32_t a;
    asm("{ .reg .u64 t; cvta.to.shared.u64 t, %1; cvt.u32.u64 %0, t; }"
        : "=r"(a) : "l"(p));
    return a;
}
__device__ __forceinline__ void cpasync16(uint32_t dst, const void* src) {
    asm volatile("cp.async.cg.shared.global [%0], [%1], 16;"
                 :: "r"(dst), "l"(src) : "memory");
}
#define CP_COMMIT() asm volatile("cp.async.commit_group;" ::: "memory")
#define CP_WAIT0()  asm volatile("cp.async.wait_group 0;" ::: "memory")

// ---------------------------------------------------------------------------
// Prep: transpose embed [256][8192] -> embedT [8192][256]
// ---------------------------------------------------------------------------
__global__ void vq_transpose(const float* __restrict__ embed) {
    __shared__ float tile[32][33];
    int jB = blockIdx.x * 32, dB = blockIdx.y * 32;
    int tx = threadIdx.x, ty = threadIdx.y;
    #pragma unroll
    for (int r = ty; r < 32; r += 8)
        tile[r][tx] = embed[(size_t)(dB + r) * NE + jB + tx];
    __syncthreads();
    #pragma unroll
    for (int r = ty; r < 32; r += 8)
        g_embedT[(size_t)(jB + r) * DIM + dB + tx] = tile[tx][r];
}

// Prep: norms (identical op order to the rel_err-0.0 R1 kernel)
__global__ void vq_norms() {
    int warp = threadIdx.x >> 5, lane = threadIdx.x & 31;
    int j = blockIdx.x * 8 + warp;
    const float4* row = (const float4*)(g_embedT + (size_t)j * DIM);
    float s = 0.f;
    #pragma unroll
    for (int i = lane; i < DIM / 4; i += 32) {
        float4 v = row[i];
        s += v.x * v.x + v.y * v.y + v.z * v.z + v.w * v.w;
    }
    #pragma unroll
    for (int o = 16; o; o >>= 1) s += __shfl_xor_sync(0xFFFFFFFFu, s, o);
    if (lane == 0) g_norms[j] = s;
}

// Prep: reset global argmin slots every launch (graph replays!)
__global__ void vq_init() {
    g_best[blockIdx.x * 256 + threadIdx.x] = 0xFFFFFFFFFFFFFFFFull;
}

// ---------------------------------------------------------------------------
// Main: FFMA GEMM + fused argmin. 8x8 microtile; B staged via cp.async
// (no RF round-trip, ~64 regs freed vs LDG+STS staging).
// grid (256, 4): x = 128-row tile, y = codebook quarter. 256 threads.
// tx = tid&15 -> 8 cols, ty = tid>>4 -> 8 rows.
// ---------------------------------------------------------------------------
__global__ void __launch_bounds__(256, 1)
vq_main(const float* __restrict__ input, const float* __restrict__ embed) {
    extern __shared__ float smem[];
    float* As = smem;                    // [256][128] : As[k*128 + m]  (128 KB)
    float* Bs = smem + 256 * 128;        // [128][128] : Bs[kk*128 + j] (64 KB)
    unsigned long long* bestP =
        (unsigned long long*)(smem + 256 * 128 + 128 * 128);           // 128
    const uint32_t sbB = smem_u32(Bs);

    const int tid = threadIdx.x;
    const int tx  = tid & 15;            // 8 cols each
    const int ty  = tid >> 4;            // 8 rows each
    const int rowBase = blockIdx.x * TM;
    const int colBase = blockIdx.y * NQ;

    if (tid < TM) bestP[tid] = 0xFFFFFFFFFFFFFFFFull;

    // ---- stage A once: 128 rows, stored transposed As[k][m] ----
    {
        const float4* Ain = (const float4*)(input + (size_t)rowBase * DIM);
        #pragma unroll
        for (int p = 0; p < 32; p++) {
            int f4 = p * 256 + tid;        // 8192 float4s (128 rows x 64 f4)
            int r  = f4 >> 6;              // row within tile
            int kb = (f4 & 63) << 2;       // k base
            float4 v = Ain[f4];
            As[(kb + 0) * TM + r] = v.x;
            As[(kb + 1) * TM + r] = v.y;
            As[(kb + 2) * TM + r] = v.z;
            As[(kb + 3) * TM + r] = v.w;
        }
    }

    unsigned int bKey[8];
    int bIdx[8];
    #pragma unroll
    for (int i = 0; i < 8; i++) { bKey[i] = 0xFFFFFFFFu; bIdx[i] = 0; }

    for (int c = 0; c < CH; c++) {
        const int cb = colBase + c * TN;

        float acc[8][8];
        #pragma unroll
        for (int i = 0; i < 8; i++)
            #pragma unroll
            for (int jj = 0; jj < 8; jj++) acc[i][jj] = 0.f;

        #pragma unroll
        for (int h = 0; h < 2; h++) {
            __syncthreads();   // previous compute done before Bs overwrite
            {
                // stage B k-half via cp.async: rows h*128.., cols cb..cb+127
                const char* Bsrc =
                    (const char*)(embed + (size_t)(h * 128) * NE + cb);
                #pragma unroll
                for (int p = 0; p < 16; p++) {
                    int f4 = p * 256 + tid;   // 4096 granules (128 k x 32)
                    int k  = f4 >> 5;
                    int jb = (f4 & 31) << 4;  // byte offset within row
                    cpasync16(sbB + (uint32_t)k * 512 + jb,
                              Bsrc + (size_t)k * (NE * 4) + jb);
                }
                CP_COMMIT();
                CP_WAIT0();
            }
            __syncthreads();

            const float* Ah = As + (h * 128) * TM;
            #pragma unroll 4
            for (int kk = 0; kk < 128; kk++) {
                float4 a0 = *(const float4*)(Ah + kk * TM + (ty << 3));
                float4 a1 = *(const float4*)(Ah + kk * TM + (ty << 3) + 4);
                float4 b0 = *(const float4*)(Bs + kk * TN + (tx << 3));
                float4 b1 = *(const float4*)(Bs + kk * TN + (tx << 3) + 4);
                float a_[8] = {a0.x, a0.y, a0.z, a0.w, a1.x, a1.y, a1.z, a1.w};
                float b_[8] = {b0.x, b0.y, b0.z, b0.w, b1.x, b1.y, b1.z, b1.w};
                #pragma unroll
                for (int i = 0; i < 8; i++)
                    #pragma unroll
                    for (int jj = 0; jj < 8; jj++)
                        acc[i][jj] = fmaf(a_[i], b_[jj], acc[i][jj]);
            }
        }

        // epilogue: score = ||e||^2 - 2*dot ; argmin with first-index ties
        #pragma unroll
        for (int jj = 0; jj < 8; jj++) {
            int jg = cb + (tx << 3) + jj;
            float nrm = g_norms[jg];
            #pragma unroll
            for (int i = 0; i < 8; i++) {
                float s = fmaf(-2.f, acc[i][jj], nrm);
                unsigned u = __float_as_uint(s);
                unsigned key = (u & 0x80000000u) ? ~u : (u | 0x80000000u);
                if (key < bKey[i]) { bKey[i] = key; bIdx[i] = jg; }
            }
        }
    }

    // ---- combine argmin: smem across threads, then global across splits ----
    #pragma unroll
    for (int i = 0; i < 8; i++) {
        unsigned long long p =
            ((unsigned long long)bKey[i] << 32) | (unsigned)bIdx[i];
        atomicMin(&bestP[(ty << 3) + i], p);
    }
    __syncthreads();

    if (tid < TM)
        atomicMin(&g_best[rowBase + tid], bestP[tid]);
}

// ---------------------------------------------------------------------------
// Finalize indices
// ---------------------------------------------------------------------------
__global__ void vq_fin(float* __restrict__ out) {
    int row = blockIdx.x * 256 + threadIdx.x;
    int j = (int)(g_best[row] & 0xFFFFFFFFull);
    g_idx[row] = j;
    out[INDOFF + row] = (float)j;
}

// ---------------------------------------------------------------------------
// Output: gather + straight-through + per-block loss partial
// ---------------------------------------------------------------------------
__global__ void __launch_bounds__(256) vq_output(const float* __restrict__ input,
                                                 float* __restrict__ out) {
    __shared__ int sIdx[64];
    __shared__ float red[256];
    const int tid = threadIdx.x;
    const int rowBase = blockIdx.x * 64;
    if (tid < 64) sIdx[tid] = g_idx[rowBase + tid];
    __syncthreads();
    float lsum = 0.f;
    for (int r = 0; r < 64; r++) {
        int j = sIdx[r];
        float q = g_embedT[(size_t)j * DIM + tid];
        float x = input[(size_t)(rowBase + r) * DIM + tid];
        float d = q - x;
        out[(size_t)(rowBase + r) * DIM + tid] = x + d;   // straight-through
        lsum += d * d;
    }
    red[tid] = lsum;
    __syncthreads();
    #pragma unroll
    for (int s = 128; s; s >>= 1) {
        if (tid < s) red[tid] += red[tid + s];
        __syncthreads();
    }
    if (tid == 0) g_partial[blockIdx.x] = red[0];
}

__global__ void vq_loss_final(float* __restrict__ out) {
    __shared__ float red[512];
    red[threadIdx.x] = g_partial[threadIdx.x];
    __syncthreads();
    #pragma unroll
    for (int s = 256; s; s >>= 1) {
        if (threadIdx.x < s) red[threadIdx.x] += red[threadIdx.x + s];
        __syncthreads();
    }
    if (threadIdx.x == 0)
        out[LOSSOFF] = red[0] * (1.0f / (float)(N_ROWS * DIM));
}

// ---------------------------------------------------------------------------
extern "C" void kernel_launch(void* const* d_in, const int* in_sizes, int n_in,
                              void* d_out, int out_size) {
    const float* input = (const float*)d_in[0];   // [8,64,64,256]
    const float* embed = (const float*)d_in[1];   // [256,8192]
    float* out = (float*)d_out;

    const int smemBytes = (256 * 128 + 128 * 128) * 4 + 128 * 8;
    cudaFuncSetAttribute(vq_main, cudaFuncAttributeMaxDynamicSharedMemorySize,
                         smemBytes);

    vq_transpose<<<dim3(NE / 32, DIM / 32), dim3(32, 8)>>>(embed);
    vq_norms<<<NE / 8, 256>>>();
    vq_init<<<N_ROWS / 256, 256>>>();
    vq_main<<<dim3(N_ROWS / TM, NSPLIT), 256, smemBytes>>>(input, embed);
    vq_fin<<<N_ROWS / 256, 256>>>(out);
    vq_output<<<N_ROWS / 64, 256>>>(input, out);
    vq_loss_final<<<1, 512>>>(out);
}